// round 2
// baseline (speedup 1.0000x reference)
#include <cuda_runtime.h>

#define UDIM 256
#define INDIM 128
#define BATCH 128
#define TLEN 1024
#define OUTD 400

// d_out layout: output [0,51200) | d_t [51200,83968) | gru1_h [83968,116736) | gru2_h [116736,149504)
#define OFF_DT   51200
#define OFF_G1   83968
#define OFF_G2   116736

#define LOG2E 1.4426950408889634f

typedef unsigned long long ull;

// scratch (no allocations allowed -> device globals)
__device__ float g_dt[BATCH * UDIM];
__device__ float g_query[BATCH * UDIM];
__device__ float g_ctx[BATCH * UDIM];

// ---------------- low-level helpers ----------------
__device__ __forceinline__ ull pk2(float x, float y) {
    ull r; asm("mov.b64 %0, {%1, %2};" : "=l"(r) : "f"(x), "f"(y)); return r;
}
__device__ __forceinline__ float2 unpk(ull a) {
    float2 v; asm("mov.b64 {%0, %1}, %2;" : "=f"(v.x), "=f"(v.y) : "l"(a)); return v;
}
__device__ __forceinline__ void fma2(ull& d, ull a, ull b) {
    asm("fma.rn.f32x2 %0, %1, %2, %0;" : "+l"(d) : "l"(a), "l"(b));
}
__device__ __forceinline__ float ex2f(float x) {
    float r; asm("ex2.approx.f32 %0, %1;" : "=f"(r) : "f"(x)); return r;
}
__device__ __forceinline__ float rcpf(float x) {
    float r; asm("rcp.approx.f32 %0, %1;" : "=f"(r) : "f"(x)); return r;
}
__device__ __forceinline__ float tanh_f(float x) {
    float xc = fminf(fmaxf(x, -10.f), 10.f);
    float e = ex2f(xc * 2.885390081777927f);   // exp(2x) = 2^(2x*log2e)
    return (e - 1.f) * rcpf(e + 1.f);
}
__device__ __forceinline__ float sigm_f(float x) {
    float xc = fminf(fmaxf(x, -30.f), 30.f);
    float e = ex2f(-LOG2E * xc);
    return rcpf(1.f + e);
}

// ================= K0: attention GRU cell + query projection =================
// 32 blocks x 256 threads; each block handles 4 batches (weights reused 4x from L2).
__global__ __launch_bounds__(256) void k0_attn_gru(
    const float* __restrict__ x, const float* __restrict__ h,
    const float* __restrict__ Wih, const float* __restrict__ Whh,
    const float* __restrict__ bih, const float* __restrict__ bhh,
    const float* __restrict__ W2, float* __restrict__ out_dt)
{
    __shared__ float xs[4][INDIM];
    __shared__ float hs[4][UDIM];
    __shared__ float dts[4][UDIM];
    int u = threadIdx.x;
    int b0 = blockIdx.x * 4;

    for (int idx = u; idx < 4 * INDIM; idx += 256)
        xs[idx >> 7][idx & 127] = x[b0 * INDIM + idx];
    for (int idx = u; idx < 4 * UDIM; idx += 256)
        hs[idx >> 8][idx & 255] = h[b0 * UDIM + idx];
    __syncthreads();

    float gr[4], gz[4], gn[4], hr[4], hz[4], hn[4];
    {
        float br = bih[u], bz = bih[UDIM + u], bn = bih[2 * UDIM + u];
        float cr = bhh[u], cz = bhh[UDIM + u], cn = bhh[2 * UDIM + u];
        #pragma unroll
        for (int bb = 0; bb < 4; bb++) {
            gr[bb] = br; gz[bb] = bz; gn[bb] = bn;
            hr[bb] = cr; hz[bb] = cz; hn[bb] = cn;
        }
    }
    const float* wr = Wih + u * INDIM;
    const float* wz = Wih + (UDIM + u) * INDIM;
    const float* wn = Wih + (2 * UDIM + u) * INDIM;
    #pragma unroll 4
    for (int j = 0; j < INDIM; j++) {
        float a = wr[j], c = wz[j], d = wn[j];
        #pragma unroll
        for (int bb = 0; bb < 4; bb++) {
            float xv = xs[bb][j];
            gr[bb] = fmaf(xv, a, gr[bb]); gz[bb] = fmaf(xv, c, gz[bb]); gn[bb] = fmaf(xv, d, gn[bb]);
        }
    }
    const float* vr = Whh + u * UDIM;
    const float* vz = Whh + (UDIM + u) * UDIM;
    const float* vn = Whh + (2 * UDIM + u) * UDIM;
    #pragma unroll 4
    for (int j = 0; j < UDIM; j++) {
        float a = vr[j], c = vz[j], d = vn[j];
        #pragma unroll
        for (int bb = 0; bb < 4; bb++) {
            float hv = hs[bb][j];
            hr[bb] = fmaf(hv, a, hr[bb]); hz[bb] = fmaf(hv, c, hz[bb]); hn[bb] = fmaf(hv, d, hn[bb]);
        }
    }
    #pragma unroll
    for (int bb = 0; bb < 4; bb++) {
        float r = sigm_f(gr[bb] + hr[bb]);
        float z = sigm_f(gz[bb] + hz[bb]);
        float n = tanh_f(gn[bb] + r * hn[bb]);
        float dv = (1.f - z) * n + z * hs[bb][u];
        dts[bb][u] = dv;
        int gi = (b0 + bb) * UDIM + u;
        g_dt[gi] = dv;
        out_dt[gi] = dv;
    }
    __syncthreads();
    // query = d_t @ W2^T
    const float* wq = W2 + u * UDIM;
    float q[4] = {0.f, 0.f, 0.f, 0.f};
    #pragma unroll 4
    for (int j = 0; j < UDIM; j++) {
        float w = wq[j];
        #pragma unroll
        for (int bb = 0; bb < 4; bb++) q[bb] = fmaf(dts[bb][j], w, q[bb]);
    }
    #pragma unroll
    for (int bb = 0; bb < 4; bb++) g_query[(b0 + bb) * UDIM + u] = q[bb];
}

// ================= K1: fused keys-GEMM + tanh scores + online softmax + context =================
// 128 blocks (one per batch) x 512 threads. T processed in 8 tiles of 128 rows.
// FFMA2 (fma.rn.f32x2) pairs adjacent n columns; W1 staged transposed per 64-k slice.
#define WT_STRIDE 258
#define SM_MT   0
#define SM_WT   32768
#define SM_SC   (SM_WT + 64 * WT_STRIDE)       // 128 scores
#define SM_ES   (SM_SC + 128)                  // 128 exp weights
#define SM_ST   (SM_ES + 128)                  // [0]=m_run [1]=sum [2]=scale
#define SM_QS   (SM_ST + 4)                    // 256 query
#define SM_VS   (SM_QS + 256)                  // 256 v
#define SM_FLOATS (SM_VS + 256)

__global__ __launch_bounds__(512, 1) void k1_attn(
    const float* __restrict__ memory, const float* __restrict__ W1,
    const float* __restrict__ vvec)
{
    extern __shared__ float sm[];
    float* Mt = sm + SM_MT;
    float* Wt = sm + SM_WT;
    float* scores_s = sm + SM_SC;
    float* e_s = sm + SM_ES;
    float* st = sm + SM_ST;
    float* q_s = sm + SM_QS;
    float* v_s = sm + SM_VS;

    int tid = threadIdx.x;
    int b = blockIdx.x;
    int tm = tid >> 5, tn = tid & 31;        // warp tm owns rows tm*8..tm*8+7
    int uu = tid & 255, half = tid >> 8;     // context accumulation role

    for (int i = tid; i < 256; i += 512) {
        q_s[i] = g_query[b * UDIM + i];
        v_s[i] = vvec[i];
    }
    if (tid == 0) { st[0] = -1e30f; st[1] = 0.f; st[2] = 0.f; }

    float ctx = 0.f;
    float srun = 0.f;
    const float* memb = memory + (size_t)b * TLEN * UDIM;

    for (int tile = 0; tile < 8; tile++) {
        int t0 = tile * 128;
        __syncthreads();   // prev tile's ctx reads of Mt/e_s complete (and smem init)
        // --- load Mt[128][256] (coalesced float4) ---
        #pragma unroll
        for (int it = 0; it < 16; it++) {
            int idx = tid + it * 512;
            int m = idx >> 6, q = idx & 63;
            float4 vld = *(const float4*)(memb + (size_t)(t0 + m) * UDIM + q * 4);
            *(float4*)(Mt + m * UDIM + q * 4) = vld;
        }

        ull acc[8][4];
        #pragma unroll
        for (int i = 0; i < 8; i++)
            #pragma unroll
            for (int c = 0; c < 4; c++) acc[i][c] = 0ull;

        for (int kt = 0; kt < 4; kt++) {
            __syncthreads();  // prev Wt consumed; Mt stores visible (kt==0)
            // stage W1[:, kt*64 .. kt*64+63] transposed -> Wt[k][n]
            #pragma unroll
            for (int it = 0; it < 8; it++) {
                int idx = tid + it * 512;
                int n = idx >> 4, q = idx & 15;
                float4 w = *(const float4*)(W1 + n * UDIM + kt * 64 + q * 4);
                Wt[(4 * q + 0) * WT_STRIDE + n] = w.x;
                Wt[(4 * q + 1) * WT_STRIDE + n] = w.y;
                Wt[(4 * q + 2) * WT_STRIDE + n] = w.z;
                Wt[(4 * q + 3) * WT_STRIDE + n] = w.w;
            }
            __syncthreads();  // Wt visible
            int kbase = kt * 64;
            #pragma unroll 2
            for (int k0 = 0; k0 < 64; k0 += 2) {
                float2 m[8];
                #pragma unroll
                for (int i = 0; i < 8; i++)
                    m[i] = *(const float2*)(Mt + (tm * 8 + i) * UDIM + kbase + k0);
                ull w0[4], w1[4];
                #pragma unroll
                for (int c = 0; c < 4; c++) {
                    w0[c] = *(const ull*)(Wt + (k0 + 0) * WT_STRIDE + 2 * (tn + 32 * c));
                    w1[c] = *(const ull*)(Wt + (k0 + 1) * WT_STRIDE + 2 * (tn + 32 * c));
                }
                #pragma unroll
                for (int i = 0; i < 8; i++) {
                    ull ax = pk2(m[i].x, m[i].x);
                    #pragma unroll
                    for (int c = 0; c < 4; c++) fma2(acc[i][c], ax, w0[c]);
                    ull ay = pk2(m[i].y, m[i].y);
                    #pragma unroll
                    for (int c = 0; c < 4; c++) fma2(acc[i][c], ay, w1[c]);
                }
            }
        }

        // --- scores: s_row = sum_n v[n]*tanh(key + q[n]) ---
        float qv0[4], qv1[4], vv0[4], vv1[4];
        #pragma unroll
        for (int c = 0; c < 4; c++) {
            int n0 = 2 * (tn + 32 * c);
            qv0[c] = q_s[n0]; qv1[c] = q_s[n0 + 1];
            vv0[c] = v_s[n0]; vv1[c] = v_s[n0 + 1];
        }
        #pragma unroll
        for (int i = 0; i < 8; i++) {
            float s = 0.f;
            #pragma unroll
            for (int c = 0; c < 4; c++) {
                float2 kv = unpk(acc[i][c]);
                s += vv0[c] * tanh_f(kv.x + qv0[c]);
                s += vv1[c] * tanh_f(kv.y + qv1[c]);
            }
            #pragma unroll
            for (int off = 16; off > 0; off >>= 1)
                s += __shfl_xor_sync(0xffffffffu, s, off);
            if (tn == 0) scores_s[tm * 8 + i] = s;
        }
        __syncthreads();  // scores ready

        // --- online softmax bookkeeping (warp 0 computes tile max) ---
        if (tid < 32) {
            float mx = -1e30f;
            #pragma unroll
            for (int j = 0; j < 4; j++) mx = fmaxf(mx, scores_s[tid + 32 * j]);
            #pragma unroll
            for (int off = 16; off > 0; off >>= 1)
                mx = fmaxf(mx, __shfl_xor_sync(0xffffffffu, mx, off));
            if (tid == 0) {
                float m_old = st[0];
                float m_new = fmaxf(m_old, mx);
                st[2] = ex2f((m_old - m_new) * LOG2E);
                st[0] = m_new;
            }
        }
        __syncthreads();
        float scale = st[2];
        float m_new = st[0];
        ctx *= scale;
        if (tid < 128) {
            float e = ex2f((scores_s[tid] - m_new) * LOG2E);
            e_s[tid] = e;
            srun = srun * scale + e;
        }
        __syncthreads();  // e_s ready

        // --- context accumulation: ctx[u] += sum_t e[t]*Mt[t][u] ---
        int tstart = half * 64;
        #pragma unroll 4
        for (int t = 0; t < 64; t++) {
            ctx = fmaf(e_s[tstart + t], Mt[(tstart + t) * UDIM + uu], ctx);
        }
    }

    __syncthreads();
    // reduce srun (threads 0..127 hold partials)
    if (tid < 128) scores_s[tid] = srun;
    Mt[half * 256 + uu] = ctx;
    __syncthreads();
    if (tid < 32) {
        float s = scores_s[tid] + scores_s[tid + 32] + scores_s[tid + 64] + scores_s[tid + 96];
        #pragma unroll
        for (int off = 16; off > 0; off >>= 1)
            s += __shfl_xor_sync(0xffffffffu, s, off);
        if (tid == 0) st[1] = s;
    }
    __syncthreads();
    float rinv = 1.f / st[1];
    if (tid < 256) g_ctx[b * UDIM + tid] = (Mt[tid] + Mt[256 + tid]) * rinv;
}

// ================= K2: proj -> GRU1 -> GRU2 -> out =================
// 32 blocks x 256 threads; 4 batches per block.
__global__ __launch_bounds__(256) void k2_tail(
    const float* __restrict__ h1in, const float* __restrict__ h2in,
    const float* __restrict__ g1_Wih, const float* __restrict__ g1_Whh,
    const float* __restrict__ g1_bih, const float* __restrict__ g1_bhh,
    const float* __restrict__ g2_Wih, const float* __restrict__ g2_Whh,
    const float* __restrict__ g2_bih, const float* __restrict__ g2_bhh,
    const float* __restrict__ proj_W, const float* __restrict__ proj_b,
    const float* __restrict__ out_W, const float* __restrict__ out_b,
    float* __restrict__ out_all)
{
    __shared__ float cat[4][2 * UDIM];
    __shared__ float gi[4][UDIM];
    __shared__ float h1s[4][UDIM];
    __shared__ float h2s[4][UDIM];
    __shared__ float g2in[4][UDIM];
    __shared__ float bf[4][UDIM];
    int u = threadIdx.x;
    int b0 = blockIdx.x * 4;

    for (int idx = u; idx < 4 * UDIM; idx += 256) {
        int bb = idx >> 8, j = idx & 255;
        cat[bb][j] = g_dt[(b0 + bb) * UDIM + j];
        cat[bb][UDIM + j] = g_ctx[(b0 + bb) * UDIM + j];
        h1s[bb][j] = h1in[(b0 + bb) * UDIM + j];
        h2s[bb][j] = h2in[(b0 + bb) * UDIM + j];
    }
    __syncthreads();

    // ---- proj: gi = cat @ proj_W^T + proj_b ----
    {
        float pb = proj_b[u];
        float a0 = pb, a1 = pb, a2 = pb, a3 = pb;
        const float* w = proj_W + u * (2 * UDIM);
        #pragma unroll 4
        for (int j = 0; j < 2 * UDIM; j++) {
            float wv = w[j];
            a0 = fmaf(cat[0][j], wv, a0);
            a1 = fmaf(cat[1][j], wv, a1);
            a2 = fmaf(cat[2][j], wv, a2);
            a3 = fmaf(cat[3][j], wv, a3);
        }
        gi[0][u] = a0; gi[1][u] = a1; gi[2][u] = a2; gi[3][u] = a3;
    }
    __syncthreads();

    // ---- GRU1 ----
    {
        float gr[4], gz[4], gn[4], hr[4], hz[4], hn[4];
        float br = g1_bih[u], bz = g1_bih[UDIM + u], bn = g1_bih[2 * UDIM + u];
        float cr = g1_bhh[u], cz = g1_bhh[UDIM + u], cn = g1_bhh[2 * UDIM + u];
        #pragma unroll
        for (int bb = 0; bb < 4; bb++) {
            gr[bb] = br; gz[bb] = bz; gn[bb] = bn;
            hr[bb] = cr; hz[bb] = cz; hn[bb] = cn;
        }
        const float* wr = g1_Wih + u * UDIM;
        const float* wz = g1_Wih + (UDIM + u) * UDIM;
        const float* wn = g1_Wih + (2 * UDIM + u) * UDIM;
        const float* vr = g1_Whh + u * UDIM;
        const float* vz = g1_Whh + (UDIM + u) * UDIM;
        const float* vn = g1_Whh + (2 * UDIM + u) * UDIM;
        #pragma unroll 4
        for (int j = 0; j < UDIM; j++) {
            float a = wr[j], c = wz[j], d = wn[j];
            float e = vr[j], f = vz[j], g = vn[j];
            #pragma unroll
            for (int bb = 0; bb < 4; bb++) {
                float xv = gi[bb][j], hv = h1s[bb][j];
                gr[bb] = fmaf(xv, a, gr[bb]); gz[bb] = fmaf(xv, c, gz[bb]); gn[bb] = fmaf(xv, d, gn[bb]);
                hr[bb] = fmaf(hv, e, hr[bb]); hz[bb] = fmaf(hv, f, hz[bb]); hn[bb] = fmaf(hv, g, hn[bb]);
            }
        }
        #pragma unroll
        for (int bb = 0; bb < 4; bb++) {
            float r = sigm_f(gr[bb] + hr[bb]);
            float z = sigm_f(gz[bb] + hz[bb]);
            float n = tanh_f(gn[bb] + r * hn[bb]);
            float hnew = (1.f - z) * n + z * h1s[bb][u];
            out_all[OFF_G1 + (b0 + bb) * UDIM + u] = hnew;
            g2in[bb][u] = gi[bb][u] + hnew;
        }
    }
    __syncthreads();

    // ---- GRU2 ----
    {
        float gr[4], gz[4], gn[4], hr[4], hz[4], hn[4];
        float br = g2_bih[u], bz = g2_bih[UDIM + u], bn = g2_bih[2 * UDIM + u];
        float cr = g2_bhh[u], cz = g2_bhh[UDIM + u], cn = g2_bhh[2 * UDIM + u];
        #pragma unroll
        for (int bb = 0; bb < 4; bb++) {
            gr[bb] = br; gz[bb] = bz; gn[bb] = bn;
            hr[bb] = cr; hz[bb] = cz; hn[bb] = cn;
        }
        const float* wr = g2_Wih + u * UDIM;
        const float* wz = g2_Wih + (UDIM + u) * UDIM;
        const float* wn = g2_Wih + (2 * UDIM + u) * UDIM;
        const float* vr = g2_Whh + u * UDIM;
        const float* vz = g2_Whh + (UDIM + u) * UDIM;
        const float* vn = g2_Whh + (2 * UDIM + u) * UDIM;
        #pragma unroll 4
        for (int j = 0; j < UDIM; j++) {
            float a = wr[j], c = wz[j], d = wn[j];
            float e = vr[j], f = vz[j], g = vn[j];
            #pragma unroll
            for (int bb = 0; bb < 4; bb++) {
                float xv = g2in[bb][j], hv = h2s[bb][j];
                gr[bb] = fmaf(xv, a, gr[bb]); gz[bb] = fmaf(xv, c, gz[bb]); gn[bb] = fmaf(xv, d, gn[bb]);
                hr[bb] = fmaf(hv, e, hr[bb]); hz[bb] = fmaf(hv, f, hz[bb]); hn[bb] = fmaf(hv, g, hn[bb]);
            }
        }
        #pragma unroll
        for (int bb = 0; bb < 4; bb++) {
            float r = sigm_f(gr[bb] + hr[bb]);
            float z = sigm_f(gz[bb] + hz[bb]);
            float n = tanh_f(gn[bb] + r * hn[bb]);
            float hnew = (1.f - z) * n + z * h2s[bb][u];
            out_all[OFF_G2 + (b0 + bb) * UDIM + u] = hnew;
            bf[bb][u] = g2in[bb][u] + hnew;
        }
    }
    __syncthreads();

    // ---- output layer: [4 x 400] ----
    for (int idx = u; idx < 4 * OUTD; idx += 256) {
        int bb = idx / OUTD;
        int o = idx - bb * OUTD;
        float a = out_b[o];
        const float* w = out_W + o * UDIM;
        #pragma unroll 4
        for (int j = 0; j < UDIM; j++) a = fmaf(bf[bb][j], w[j], a);
        out_all[(b0 + bb) * OUTD + o] = a;
    }
}

extern "C" void kernel_launch(void* const* d_in, const int* in_sizes, int n_in,
                              void* d_out, int out_size) {
    const float* decoder_input = (const float*)d_in[0];
    const float* memory        = (const float*)d_in[1];
    const float* attn_hidden   = (const float*)d_in[2];
    const float* gru1_hidden   = (const float*)d_in[3];
    const float* gru2_hidden   = (const float*)d_in[4];
    const float* W1            = (const float*)d_in[5];
    const float* W2            = (const float*)d_in[6];
    const float* v             = (const float*)d_in[7];
    const float* attn_Wih      = (const float*)d_in[8];
    const float* attn_Whh      = (const float*)d_in[9];
    const float* attn_bih      = (const float*)d_in[10];
    const float* attn_bhh      = (const float*)d_in[11];
    const float* g1_Wih        = (const float*)d_in[12];
    const float* g1_Whh        = (const float*)d_in[13];
    const float* g1_bih        = (const float*)d_in[14];
    const float* g1_bhh        = (const float*)d_in[15];
    const float* g2_Wih        = (const float*)d_in[16];
    const float* g2_Whh        = (const float*)d_in[17];
    const float* g2_bih        = (const float*)d_in[18];
    const float* g2_bhh        = (const float*)d_in[19];
    const float* proj_W        = (const float*)d_in[20];
    const float* proj_b        = (const float*)d_in[21];
    const float* out_W         = (const float*)d_in[22];
    const float* out_b         = (const float*)d_in[23];
    float* out = (float*)d_out;

    int smem_bytes = SM_FLOATS * sizeof(float);
    cudaFuncSetAttribute(k1_attn, cudaFuncAttributeMaxDynamicSharedMemorySize, smem_bytes);

    k0_attn_gru<<<32, 256>>>(decoder_input, attn_hidden,
                             attn_Wih, attn_Whh, attn_bih, attn_bhh,
                             W2, out + OFF_DT);
    k1_attn<<<128, 512, smem_bytes>>>(memory, W1, v);
    k2_tail<<<32, 256>>>(gru1_hidden, gru2_hidden,
                         g1_Wih, g1_Whh, g1_bih, g1_bhh,
                         g2_Wih, g2_Whh, g2_bih, g2_bhh,
                         proj_W, proj_b, out_W, out_b, out);
}

// round 4
// speedup vs baseline: 1.4348x; 1.4348x over previous
#include <cuda_runtime.h>

#define UDIM 256
#define INDIM 128
#define BATCH 128
#define TLEN 1024
#define OUTD 400

// d_out layout: output [0,51200) | d_t [51200,83968) | gru1_h [83968,116736) | gru2_h [116736,149504)
#define OFF_DT   51200
#define OFF_G1   83968
#define OFF_G2   116736

#define LOG2E 1.4426950408889634f

typedef unsigned long long ull;

// scratch (no allocations allowed -> device globals)
__device__ float g_dt[BATCH * UDIM];
__device__ float g_query[BATCH * UDIM];
__device__ float g_ctx[BATCH * UDIM];

// ---------------- low-level helpers ----------------
__device__ __forceinline__ ull pk2(float x, float y) {
    ull r; asm("mov.b64 %0, {%1, %2};" : "=l"(r) : "f"(x), "f"(y)); return r;
}
__device__ __forceinline__ float2 unpk(ull a) {
    float2 v; asm("mov.b64 {%0, %1}, %2;" : "=f"(v.x), "=f"(v.y) : "l"(a)); return v;
}
__device__ __forceinline__ void fma2(ull& d, ull a, ull b) {
    asm("fma.rn.f32x2 %0, %1, %2, %0;" : "+l"(d) : "l"(a), "l"(b));
}
__device__ __forceinline__ float ex2f(float x) {
    float r; asm("ex2.approx.f32 %0, %1;" : "=f"(r) : "f"(x)); return r;
}
__device__ __forceinline__ float rcpf(float x) {
    float r; asm("rcp.approx.f32 %0, %1;" : "=f"(r) : "f"(x)); return r;
}
__device__ __forceinline__ float tanh_f(float x) {
    float xc = fminf(fmaxf(x, -10.f), 10.f);
    float e = ex2f(xc * 2.885390081777927f);   // exp(2x)
    return (e - 1.f) * rcpf(e + 1.f);
}
__device__ __forceinline__ float sigm_f(float x) {
    float xc = fminf(fmaxf(x, -30.f), 30.f);
    float e = ex2f(-LOG2E * xc);
    return rcpf(1.f + e);
}

// ---------------- shared matvec helper (256 threads, 4 batches) ----------------
// out[u] over 256 outputs. Weights W row-major [256][K].
// Stages 32-k slices transposed into ws[32*257]; inputs are smem row pointers.
__device__ __forceinline__ void mv4(
    const float* __restrict__ W, int K,
    const float* __restrict__ i0, const float* __restrict__ i1,
    const float* __restrict__ i2, const float* __restrict__ i3,
    float* __restrict__ ws, int tid, float acc[4])
{
    int u = tid;
    for (int kt = 0; kt < K; kt += 32) {
        __syncthreads();
        #pragma unroll
        for (int it = 0; it < 8; it++) {
            int task = tid + it * 256;
            int uu = task >> 3, kc = task & 7;
            float4 w = *(const float4*)(W + uu * K + kt + kc * 4);
            ws[(kc * 4 + 0) * 257 + uu] = w.x;
            ws[(kc * 4 + 1) * 257 + uu] = w.y;
            ws[(kc * 4 + 2) * 257 + uu] = w.z;
            ws[(kc * 4 + 3) * 257 + uu] = w.w;
        }
        __syncthreads();
        #pragma unroll 8
        for (int k = 0; k < 32; k++) {
            float wv = ws[k * 257 + u];
            acc[0] = fmaf(i0[kt + k], wv, acc[0]);
            acc[1] = fmaf(i1[kt + k], wv, acc[1]);
            acc[2] = fmaf(i2[kt + k], wv, acc[2]);
            acc[3] = fmaf(i3[kt + k], wv, acc[3]);
        }
    }
}

// ================= K0: attention GRU cell + query projection =================
// 32 blocks x 256 threads; 4 batches per block; smem-staged weights.
__global__ __launch_bounds__(256) void k0_attn_gru(
    const float* __restrict__ x, const float* __restrict__ h,
    const float* __restrict__ Wih, const float* __restrict__ Whh,
    const float* __restrict__ bih, const float* __restrict__ bhh,
    const float* __restrict__ W2, float* __restrict__ out_dt)
{
    __shared__ float xs[4][INDIM];
    __shared__ float hs[4][UDIM];
    __shared__ float dts[4][UDIM];
    __shared__ float ws[32 * 257];
    int u = threadIdx.x;
    int b0 = blockIdx.x * 4;

    for (int idx = u; idx < 4 * INDIM; idx += 256)
        xs[idx >> 7][idx & 127] = x[b0 * INDIM + idx];
    for (int idx = u; idx < 4 * UDIM; idx += 256)
        hs[idx >> 8][idx & 255] = h[b0 * UDIM + idx];

    float gr[4], gz[4], gn[4], hr[4], hz[4], hn[4];
    {
        float br = bih[u], bz = bih[UDIM + u], bn = bih[2 * UDIM + u];
        float cr = bhh[u], cz = bhh[UDIM + u], cn = bhh[2 * UDIM + u];
        #pragma unroll
        for (int bb = 0; bb < 4; bb++) {
            gr[bb] = br; gz[bb] = bz; gn[bb] = bn;
            hr[bb] = cr; hz[bb] = cz; hn[bb] = cn;
        }
    }
    mv4(Wih,                      INDIM, xs[0], xs[1], xs[2], xs[3], ws, u, gr);
    mv4(Wih + UDIM * INDIM,       INDIM, xs[0], xs[1], xs[2], xs[3], ws, u, gz);
    mv4(Wih + 2 * UDIM * INDIM,   INDIM, xs[0], xs[1], xs[2], xs[3], ws, u, gn);
    mv4(Whh,                      UDIM,  hs[0], hs[1], hs[2], hs[3], ws, u, hr);
    mv4(Whh + UDIM * UDIM,        UDIM,  hs[0], hs[1], hs[2], hs[3], ws, u, hz);
    mv4(Whh + 2 * UDIM * UDIM,    UDIM,  hs[0], hs[1], hs[2], hs[3], ws, u, hn);

    #pragma unroll
    for (int bb = 0; bb < 4; bb++) {
        float r = sigm_f(gr[bb] + hr[bb]);
        float z = sigm_f(gz[bb] + hz[bb]);
        float n = tanh_f(gn[bb] + r * hn[bb]);
        float dv = (1.f - z) * n + z * hs[bb][u];
        dts[bb][u] = dv;
        int gi = (b0 + bb) * UDIM + u;
        g_dt[gi] = dv;
        out_dt[gi] = dv;
    }
    // query = d_t @ W2^T  (dts written by thread u; mv4's leading sync covers)
    float q[4] = {0.f, 0.f, 0.f, 0.f};
    mv4(W2, UDIM, dts[0], dts[1], dts[2], dts[3], ws, u, q);
    #pragma unroll
    for (int bb = 0; bb < 4; bb++) g_query[(b0 + bb) * UDIM + u] = q[bb];
}

// ================= K1: fused keys-GEMM + tanh scores + online softmax + context =================
// 128 blocks (one per batch) x 512 threads (16 warps, 4x4 warp grid).
// Warp tile 32 rows x 64 n. Thread: rows rowbase + 4p (lo) / +16 (hi), n = nbase + 8j.
// K=256 in 16 double-buffered 16-k W1 slices (pre-duplicated ull).
#define MT_STRIDE 260
#define WT2_ROW 257
#define WT2_HALF (16 * 257)
#define OFF_MT  0
#define OFF_WT2 (128 * MT_STRIDE)
#define OFF_SCP (OFF_WT2 + 2 * WT2_HALF * 2)
#define OFF_SC  (OFF_SCP + 4 * 132)
#define OFF_ES  (OFF_SC + 128)
#define OFF_ST  (OFF_ES + 128)
#define OFF_QS  (OFF_ST + 8)
#define OFF_VS  (OFF_QS + 256)
#define OFF_CTX (OFF_VS + 256)
#define K1_SMEM_FLOATS (OFF_CTX + 512)

__global__ __launch_bounds__(512, 1) void k1_attn(
    const float* __restrict__ memory, const float* __restrict__ W1,
    const float* __restrict__ vvec)
{
    extern __shared__ float sm[];
    float* Mt = sm + OFF_MT;
    ull*   Wt2 = (ull*)(sm + OFF_WT2);
    float* scp = sm + OFF_SCP;
    float* scores_s = sm + OFF_SC;
    float* e_s = sm + OFF_ES;
    float* st = sm + OFF_ST;
    float* q_s = sm + OFF_QS;
    float* v_s = sm + OFF_VS;
    float* ctx_s = sm + OFF_CTX;

    int tid = threadIdx.x;
    int b = blockIdx.x;
    int wid = tid >> 5, lane = tid & 31;
    int warpR = wid >> 2, warpC = wid & 3;
    int r_l = lane >> 3, c_l = lane & 7;
    int rowbase = warpR * 32 + r_l;          // thread rows: rowbase + 4p, rowbase + 4p + 16
    int nbase = warpC * 64 + c_l;            // n = nbase + 8j
    int uu = tid & 255, half = tid >> 8;

    for (int i = tid; i < 256; i += 512) {
        q_s[i] = g_query[b * UDIM + i];
        v_s[i] = vvec[i];
    }
    if (tid == 0) { st[0] = -1e30f; st[1] = 0.f; st[2] = 0.f; }

    float ctx = 0.f;
    float srun = 0.f;
    const float* memb = memory + (size_t)b * TLEN * UDIM;

    // slice staging: 512 threads x 2 float4 (n and n+128), 16 k per slice
    int sn0 = tid >> 2, skc = tid & 3;

    for (int tile = 0; tile < 8; tile++) {
        int t0 = tile * 128;
        __syncthreads();   // prev tile consumers done; smem reusable
        // --- load Mt[128][256] (stride 260) ---
        #pragma unroll
        for (int it = 0; it < 16; it++) {
            int idx = tid + it * 512;
            int m = idx >> 6, q = idx & 63;
            float4 vld = *(const float4*)(memb + (size_t)(t0 + m) * UDIM + q * 4);
            *(float4*)(Mt + m * MT_STRIDE + q * 4) = vld;
        }

        ull acc[4][8];
        #pragma unroll
        for (int p = 0; p < 4; p++)
            #pragma unroll
            for (int j = 0; j < 8; j++) acc[p][j] = 0ull;

        // prefetch slice 0
        float4 w0 = *(const float4*)(W1 + sn0 * UDIM + 0 + skc * 4);
        float4 w1 = *(const float4*)(W1 + (sn0 + 128) * UDIM + 0 + skc * 4);

        for (int s = 0; s < 16; s++) {
            // store current slice (duplicated {w,w}) into buffer s&1
            float* wf = (float*)(Wt2 + (s & 1) * WT2_HALF);
            {
                int kb = skc * 4;
                int i0 = ((kb + 0) * WT2_ROW + sn0) * 2;
                int i1 = ((kb + 1) * WT2_ROW + sn0) * 2;
                int i2 = ((kb + 2) * WT2_ROW + sn0) * 2;
                int i3 = ((kb + 3) * WT2_ROW + sn0) * 2;
                wf[i0] = w0.x; wf[i0 + 1] = w0.x;
                wf[i1] = w0.y; wf[i1 + 1] = w0.y;
                wf[i2] = w0.z; wf[i2 + 1] = w0.z;
                wf[i3] = w0.w; wf[i3 + 1] = w0.w;
                int j0 = i0 + 256, j1 = i1 + 256, j2 = i2 + 256, j3 = i3 + 256;
                wf[j0] = w1.x; wf[j0 + 1] = w1.x;
                wf[j1] = w1.y; wf[j1 + 1] = w1.y;
                wf[j2] = w1.z; wf[j2 + 1] = w1.z;
                wf[j3] = w1.w; wf[j3 + 1] = w1.w;
            }
            __syncthreads();
            // prefetch next slice while GEMM runs
            if (s < 15) {
                int kb = (s + 1) * 16;
                w0 = *(const float4*)(W1 + sn0 * UDIM + kb + skc * 4);
                w1 = *(const float4*)(W1 + (sn0 + 128) * UDIM + kb + skc * 4);
            }
            // --- GEMM on slice s ---
            const ull* wb = Wt2 + (s & 1) * WT2_HALF + nbase;
            const float* mb = Mt + rowbase * MT_STRIDE + s * 16;
            #pragma unroll 2
            for (int k = 0; k < 16; k++) {
                ull bfr[8];
                #pragma unroll
                for (int j = 0; j < 8; j++) bfr[j] = wb[k * WT2_ROW + 8 * j];
                #pragma unroll
                for (int p = 0; p < 4; p++) {
                    float alo = mb[(4 * p) * MT_STRIDE + k];
                    float ahi = mb[(4 * p + 16) * MT_STRIDE + k];
                    ull a = pk2(alo, ahi);
                    #pragma unroll
                    for (int j = 0; j < 8; j++) fma2(acc[p][j], a, bfr[j]);
                }
            }
        }

        // --- scores epilogue: s_row = sum_n v[n]*tanh(key + q[n]) ---
        {
            float qv[8], vv[8];
            #pragma unroll
            for (int j = 0; j < 8; j++) {
                qv[j] = q_s[nbase + 8 * j];
                vv[j] = v_s[nbase + 8 * j];
            }
            float slo[4] = {0.f, 0.f, 0.f, 0.f};
            float shi[4] = {0.f, 0.f, 0.f, 0.f};
            #pragma unroll
            for (int p = 0; p < 4; p++) {
                #pragma unroll
                for (int j = 0; j < 8; j++) {
                    float2 kv = unpk(acc[p][j]);
                    slo[p] = fmaf(vv[j], tanh_f(kv.x + qv[j]), slo[p]);
                    shi[p] = fmaf(vv[j], tanh_f(kv.y + qv[j]), shi[p]);
                }
            }
            #pragma unroll
            for (int p = 0; p < 4; p++) {
                #pragma unroll
                for (int off = 1; off <= 4; off <<= 1) {
                    slo[p] += __shfl_xor_sync(0xffffffffu, slo[p], off);
                    shi[p] += __shfl_xor_sync(0xffffffffu, shi[p], off);
                }
            }
            if (c_l == 0) {
                #pragma unroll
                for (int p = 0; p < 4; p++) {
                    scp[warpC * 132 + rowbase + 4 * p] = slo[p];
                    scp[warpC * 132 + rowbase + 4 * p + 16] = shi[p];
                }
            }
        }
        __syncthreads();
        if (tid < 128)
            scores_s[tid] = scp[tid] + scp[132 + tid] + scp[264 + tid] + scp[396 + tid];
        __syncthreads();
        if (tid < 32) {
            float mx = fmaxf(fmaxf(scores_s[tid], scores_s[tid + 32]),
                             fmaxf(scores_s[tid + 64], scores_s[tid + 96]));
            #pragma unroll
            for (int off = 16; off > 0; off >>= 1)
                mx = fmaxf(mx, __shfl_xor_sync(0xffffffffu, mx, off));
            if (tid == 0) {
                float m_old = st[0];
                float m_new = fmaxf(m_old, mx);
                st[2] = ex2f((m_old - m_new) * LOG2E);
                st[0] = m_new;
            }
        }
        __syncthreads();
        float scale = st[2];
        float m_new = st[0];
        ctx *= scale;
        if (tid < 128) {
            float e = ex2f((scores_s[tid] - m_new) * LOG2E);
            e_s[tid] = e;
            srun = srun * scale + e;
        }
        __syncthreads();  // e_s ready

        // --- context accumulation: ctx[u] += sum_t e[t]*Mt[t][u] ---
        int tstart = half * 64;
        #pragma unroll 4
        for (int t = 0; t < 64; t++)
            ctx = fmaf(e_s[tstart + t], Mt[(tstart + t) * MT_STRIDE + uu], ctx);
    }

    __syncthreads();
    if (tid < 128) scores_s[tid] = srun;
    ctx_s[half * 256 + uu] = ctx;
    __syncthreads();
    if (tid < 32) {
        float s = scores_s[tid] + scores_s[tid + 32] + scores_s[tid + 64] + scores_s[tid + 96];
        #pragma unroll
        for (int off = 16; off > 0; off >>= 1)
            s += __shfl_xor_sync(0xffffffffu, s, off);
        if (tid == 0) st[1] = s;
    }
    __syncthreads();
    float rinv = 1.f / st[1];
    if (tid < 256) g_ctx[b * UDIM + tid] = (ctx_s[tid] + ctx_s[256 + tid]) * rinv;
}

// ================= K2: proj -> GRU1 -> GRU2 -> out =================
// 32 blocks x 256 threads; 4 batches per block; smem-staged weights; dynamic smem.
#define K2_CAT   0
#define K2_GI    (K2_CAT + 4 * 512)
#define K2_H1    (K2_GI + 4 * 256)
#define K2_H2    (K2_H1 + 4 * 256)
#define K2_G2IN  (K2_H2 + 4 * 256)
#define K2_BF    (K2_G2IN + 4 * 256)
#define K2_WS    (K2_BF + 4 * 256)
#define K2_SMEM_FLOATS (K2_WS + 32 * 257)

__global__ __launch_bounds__(256) void k2_tail(
    const float* __restrict__ h1in, const float* __restrict__ h2in,
    const float* __restrict__ g1_Wih, const float* __restrict__ g1_Whh,
    const float* __restrict__ g1_bih, const float* __restrict__ g1_bhh,
    const float* __restrict__ g2_Wih, const float* __restrict__ g2_Whh,
    const float* __restrict__ g2_bih, const float* __restrict__ g2_bhh,
    const float* __restrict__ proj_W, const float* __restrict__ proj_b,
    const float* __restrict__ out_W, const float* __restrict__ out_b,
    float* __restrict__ out_all)
{
    extern __shared__ float sm[];
    float* cat  = sm + K2_CAT;    // [4][512]
    float* gi   = sm + K2_GI;     // [4][256]
    float* h1s  = sm + K2_H1;
    float* h2s  = sm + K2_H2;
    float* g2in = sm + K2_G2IN;
    float* bfs  = sm + K2_BF;
    float* ws   = sm + K2_WS;
    int u = threadIdx.x;
    int b0 = blockIdx.x * 4;

    for (int idx = u; idx < 4 * UDIM; idx += 256) {
        int bb = idx >> 8, j = idx & 255;
        cat[bb * 512 + j] = g_dt[(b0 + bb) * UDIM + j];
        cat[bb * 512 + UDIM + j] = g_ctx[(b0 + bb) * UDIM + j];
        h1s[bb * 256 + j] = h1in[(b0 + bb) * UDIM + j];
        h2s[bb * 256 + j] = h2in[(b0 + bb) * UDIM + j];
    }

    // ---- proj ----
    {
        float pb = proj_b[u];
        float a[4] = {pb, pb, pb, pb};
        mv4(proj_W, 2 * UDIM, cat, cat + 512, cat + 1024, cat + 1536, ws, u, a);
        gi[u] = a[0]; gi[256 + u] = a[1]; gi[512 + u] = a[2]; gi[768 + u] = a[3];
    }

    // ---- GRU1 ----
    {
        float gr[4], gz[4], gn[4], hr[4], hz[4], hn[4];
        float br = g1_bih[u], bz = g1_bih[UDIM + u], bn = g1_bih[2 * UDIM + u];
        float cr = g1_bhh[u], cz = g1_bhh[UDIM + u], cn = g1_bhh[2 * UDIM + u];
        #pragma unroll
        for (int bb = 0; bb < 4; bb++) {
            gr[bb] = br; gz[bb] = bz; gn[bb] = bn;
            hr[bb] = cr; hz[bb] = cz; hn[bb] = cn;
        }
        mv4(g1_Wih,                    UDIM, gi, gi + 256, gi + 512, gi + 768, ws, u, gr);
        mv4(g1_Wih + UDIM * UDIM,      UDIM, gi, gi + 256, gi + 512, gi + 768, ws, u, gz);
        mv4(g1_Wih + 2 * UDIM * UDIM,  UDIM, gi, gi + 256, gi + 512, gi + 768, ws, u, gn);
        mv4(g1_Whh,                    UDIM, h1s, h1s + 256, h1s + 512, h1s + 768, ws, u, hr);
        mv4(g1_Whh + UDIM * UDIM,      UDIM, h1s, h1s + 256, h1s + 512, h1s + 768, ws, u, hz);
        mv4(g1_Whh + 2 * UDIM * UDIM,  UDIM, h1s, h1s + 256, h1s + 512, h1s + 768, ws, u, hn);
        #pragma unroll
        for (int bb = 0; bb < 4; bb++) {
            float r = sigm_f(gr[bb] + hr[bb]);
            float z = sigm_f(gz[bb] + hz[bb]);
            float n = tanh_f(gn[bb] + r * hn[bb]);
            float hnew = (1.f - z) * n + z * h1s[bb * 256 + u];
            out_all[OFF_G1 + (b0 + bb) * UDIM + u] = hnew;
            g2in[bb * 256 + u] = gi[bb * 256 + u] + hnew;
        }
    }

    // ---- GRU2 ----
    {
        float gr[4], gz[4], gn[4], hr[4], hz[4], hn[4];
        float br = g2_bih[u], bz = g2_bih[UDIM + u], bn = g2_bih[2 * UDIM + u];
        float cr = g2_bhh[u], cz = g2_bhh[UDIM + u], cn = g2_bhh[2 * UDIM + u];
        #pragma unroll
        for (int bb = 0; bb < 4; bb++) {
            gr[bb] = br; gz[bb] = bz; gn[bb] = bn;
            hr[bb] = cr; hz[bb] = cz; hn[bb] = cn;
        }
        mv4(g2_Wih,                    UDIM, g2in, g2in + 256, g2in + 512, g2in + 768, ws, u, gr);
        mv4(g2_Wih + UDIM * UDIM,      UDIM, g2in, g2in + 256, g2in + 512, g2in + 768, ws, u, gz);
        mv4(g2_Wih + 2 * UDIM * UDIM,  UDIM, g2in, g2in + 256, g2in + 512, g2in + 768, ws, u, gn);
        mv4(g2_Whh,                    UDIM, h2s, h2s + 256, h2s + 512, h2s + 768, ws, u, hr);
        mv4(g2_Whh + UDIM * UDIM,      UDIM, h2s, h2s + 256, h2s + 512, h2s + 768, ws, u, hz);
        mv4(g2_Whh + 2 * UDIM * UDIM,  UDIM, h2s, h2s + 256, h2s + 512, h2s + 768, ws, u, hn);
        #pragma unroll
        for (int bb = 0; bb < 4; bb++) {
            float r = sigm_f(gr[bb] + hr[bb]);
            float z = sigm_f(gz[bb] + hz[bb]);
            float n = tanh_f(gn[bb] + r * hn[bb]);
            float hnew = (1.f - z) * n + z * h2s[bb * 256 + u];
            out_all[OFF_G2 + (b0 + bb) * UDIM + u] = hnew;
            bfs[bb * 256 + u] = g2in[bb * 256 + u] + hnew;
        }
    }
    __syncthreads();

    // ---- output layer: [4 x 400] per-thread float4 streaming ----
    for (int o = u; o < OUTD; o += 256) {
        float ob = out_b[o];
        float a0 = ob, a1 = ob, a2 = ob, a3 = ob;
        const float4* w4 = (const float4*)(out_W + o * UDIM);
        #pragma unroll 8
        for (int j4 = 0; j4 < 64; j4++) {
            float4 w = w4[j4];
            int j = j4 * 4;
            a0 = fmaf(bfs[j], w.x, fmaf(bfs[j + 1], w.y, fmaf(bfs[j + 2], w.z, fmaf(bfs[j + 3], w.w, a0))));
            a1 = fmaf(bfs[256 + j], w.x, fmaf(bfs[257 + j], w.y, fmaf(bfs[258 + j], w.z, fmaf(bfs[259 + j], w.w, a1))));
            a2 = fmaf(bfs[512 + j], w.x, fmaf(bfs[513 + j], w.y, fmaf(bfs[514 + j], w.z, fmaf(bfs[515 + j], w.w, a2))));
            a3 = fmaf(bfs[768 + j], w.x, fmaf(bfs[769 + j], w.y, fmaf(bfs[770 + j], w.z, fmaf(bfs[771 + j], w.w, a3))));
        }
        out_all[(b0 + 0) * OUTD + o] = a0;
        out_all[(b0 + 1) * OUTD + o] = a1;
        out_all[(b0 + 2) * OUTD + o] = a2;
        out_all[(b0 + 3) * OUTD + o] = a3;
    }
}

extern "C" void kernel_launch(void* const* d_in, const int* in_sizes, int n_in,
                              void* d_out, int out_size) {
    const float* decoder_input = (const float*)d_in[0];
    const float* memory        = (const float*)d_in[1];
    const float* attn_hidden   = (const float*)d_in[2];
    const float* gru1_hidden   = (const float*)d_in[3];
    const float* gru2_hidden   = (const float*)d_in[4];
    const float* W1            = (const float*)d_in[5];
    const float* W2            = (const float*)d_in[6];
    const float* v             = (const float*)d_in[7];
    const float* attn_Wih      = (const float*)d_in[8];
    const float* attn_Whh      = (const float*)d_in[9];
    const float* attn_bih      = (const float*)d_in[10];
    const float* attn_bhh      = (const float*)d_in[11];
    const float* g1_Wih        = (const float*)d_in[12];
    const float* g1_Whh        = (const float*)d_in[13];
    const float* g1_bih        = (const float*)d_in[14];
    const float* g1_bhh        = (const float*)d_in[15];
    const float* g2_Wih        = (const float*)d_in[16];
    const float* g2_Whh        = (const float*)d_in[17];
    const float* g2_bih        = (const float*)d_in[18];
    const float* g2_bhh        = (const float*)d_in[19];
    const float* proj_W        = (const float*)d_in[20];
    const float* proj_b        = (const float*)d_in[21];
    const float* out_W         = (const float*)d_in[22];
    const float* out_b         = (const float*)d_in[23];
    float* out = (float*)d_out;

    int k1_smem = K1_SMEM_FLOATS * sizeof(float);
    int k2_smem = K2_SMEM_FLOATS * sizeof(float);
    cudaFuncSetAttribute(k1_attn, cudaFuncAttributeMaxDynamicSharedMemorySize, k1_smem);
    cudaFuncSetAttribute(k2_tail, cudaFuncAttributeMaxDynamicSharedMemorySize, k2_smem);

    k0_attn_gru<<<32, 256>>>(decoder_input, attn_hidden,
                             attn_Wih, attn_Whh, attn_bih, attn_bhh,
                             W2, out + OFF_DT);
    k1_attn<<<128, 512, k1_smem>>>(memory, W1, v);
    k2_tail<<<32, 256, k2_smem>>>(gru1_hidden, gru2_hidden,
                                  g1_Wih, g1_Whh, g1_bih, g1_bhh,
                                  g2_Wih, g2_Whh, g2_bih, g2_bhh,
                                  proj_W, proj_b, out_W, out_b, out);
}

// round 5
// speedup vs baseline: 1.5195x; 1.0591x over previous
#include <cuda_runtime.h>

#define UDIM 256
#define INDIM 128
#define BATCH 128
#define TLEN 1024
#define OUTD 400

// d_out layout: output [0,51200) | d_t [51200,83968) | gru1_h [83968,116736) | gru2_h [116736,149504)
#define OFF_DT   51200
#define OFF_G1   83968
#define OFF_G2   116736

#define LOG2E 1.4426950408889634f

typedef unsigned long long ull;

// scratch (no allocations allowed -> device globals)
__device__ float g_dt[BATCH * UDIM];
__device__ float g_query[BATCH * UDIM];
__device__ float g_ctx[BATCH * UDIM];

// ---------------- low-level helpers ----------------
__device__ __forceinline__ ull pk2(float x, float y) {
    ull r; asm("mov.b64 %0, {%1, %2};" : "=l"(r) : "f"(x), "f"(y)); return r;
}
__device__ __forceinline__ float2 unpk(ull a) {
    float2 v; asm("mov.b64 {%0, %1}, %2;" : "=f"(v.x), "=f"(v.y) : "l"(a)); return v;
}
__device__ __forceinline__ void fma2(ull& d, ull a, ull b) {
    asm("fma.rn.f32x2 %0, %1, %2, %0;" : "+l"(d) : "l"(a), "l"(b));
}
__device__ __forceinline__ float ex2f(float x) {
    float r; asm("ex2.approx.f32 %0, %1;" : "=f"(r) : "f"(x)); return r;
}
__device__ __forceinline__ float rcpf(float x) {
    float r; asm("rcp.approx.f32 %0, %1;" : "=f"(r) : "f"(x)); return r;
}
__device__ __forceinline__ float tanh_f(float x) {
    float xc = fminf(fmaxf(x, -10.f), 10.f);
    float e = ex2f(xc * 2.885390081777927f);   // exp(2x)
    return (e - 1.f) * rcpf(e + 1.f);
}
__device__ __forceinline__ float sigm_f(float x) {
    float xc = fminf(fmaxf(x, -30.f), 30.f);
    float e = ex2f(-LOG2E * xc);
    return rcpf(1.f + e);
}

// ---------------- mv4b: batched matvec, 256 threads, 4 batches ----------------
// out[u] over 256 outputs; W row-major [256][K], K in {128,256,512} (nslices even).
// Verbatim staging (no transpose): ws[2][256][36], thread u computes from its own
// row via LDS.128. Double-buffered: register prefetch of the next 32-k slice
// overlaps the current slice's compute; ONE barrier per slice.
#define WS2_STRIDE 36
#define WS2_HALF (256 * WS2_STRIDE)

__device__ __forceinline__ void mv4b(
    const float* __restrict__ W, int K,
    const float* __restrict__ i0, const float* __restrict__ i1,
    const float* __restrict__ i2, const float* __restrict__ i3,
    float* __restrict__ ws, int tid, float acc[4])
{
    int uu = tid >> 3, kc = tid & 7;   // staging: rows uu+32*it, k-chunk kc
    int nslices = K >> 5;
    float4 pf[8];
    #pragma unroll
    for (int it = 0; it < 8; it++)
        pf[it] = *(const float4*)(W + (uu + 32 * it) * K + kc * 4);

    for (int s = 0; s < nslices; s++) {
        float* wbuf = ws + (s & 1) * WS2_HALF;
        #pragma unroll
        for (int it = 0; it < 8; it++)
            *(float4*)(wbuf + (uu + 32 * it) * WS2_STRIDE + kc * 4) = pf[it];
        __syncthreads();
        if (s + 1 < nslices) {
            int ktn = (s + 1) << 5;
            #pragma unroll
            for (int it = 0; it < 8; it++)
                pf[it] = *(const float4*)(W + (uu + 32 * it) * K + ktn + kc * 4);
        }
        int kt = s << 5;
        const float* wrow = wbuf + tid * WS2_STRIDE;
        #pragma unroll
        for (int kk = 0; kk < 8; kk++) {
            float4 w  = *(const float4*)(wrow + kk * 4);
            float4 a0 = *(const float4*)(i0 + kt + kk * 4);
            float4 a1 = *(const float4*)(i1 + kt + kk * 4);
            float4 a2 = *(const float4*)(i2 + kt + kk * 4);
            float4 a3 = *(const float4*)(i3 + kt + kk * 4);
            acc[0] = fmaf(a0.x, w.x, fmaf(a0.y, w.y, fmaf(a0.z, w.z, fmaf(a0.w, w.w, acc[0]))));
            acc[1] = fmaf(a1.x, w.x, fmaf(a1.y, w.y, fmaf(a1.z, w.z, fmaf(a1.w, w.w, acc[1]))));
            acc[2] = fmaf(a2.x, w.x, fmaf(a2.y, w.y, fmaf(a2.z, w.z, fmaf(a2.w, w.w, acc[2]))));
            acc[3] = fmaf(a3.x, w.x, fmaf(a3.y, w.y, fmaf(a3.z, w.z, fmaf(a3.w, w.w, acc[3]))));
        }
    }
}

// ================= K0: attention GRU cell + query projection =================
// 32 blocks x 256 threads; 4 batches per block.
#define K0_XS   0
#define K0_HS   (K0_XS + 4 * INDIM)
#define K0_DTS  (K0_HS + 4 * UDIM)
#define K0_WS   (K0_DTS + 4 * UDIM)
#define K0_SMEM_FLOATS (K0_WS + 2 * WS2_HALF)

__global__ __launch_bounds__(256) void k0_attn_gru(
    const float* __restrict__ x, const float* __restrict__ h,
    const float* __restrict__ Wih, const float* __restrict__ Whh,
    const float* __restrict__ bih, const float* __restrict__ bhh,
    const float* __restrict__ W2, float* __restrict__ out_dt)
{
    extern __shared__ float sm[];
    float* xs  = sm + K0_XS;    // [4][128]
    float* hs  = sm + K0_HS;    // [4][256]
    float* dts = sm + K0_DTS;   // [4][256]
    float* ws  = sm + K0_WS;
    int u = threadIdx.x;
    int b0 = blockIdx.x * 4;

    for (int idx = u; idx < 4 * INDIM; idx += 256)
        xs[idx] = x[b0 * INDIM + idx];
    for (int idx = u; idx < 4 * UDIM; idx += 256)
        hs[idx] = h[b0 * UDIM + idx];
    // mv4b's first barrier orders these writes before any compute read.

    float gr[4], gz[4], gn[4], hr[4], hz[4], hn[4];
    {
        float br = bih[u], bz = bih[UDIM + u], bn = bih[2 * UDIM + u];
        float cr = bhh[u], cz = bhh[UDIM + u], cn = bhh[2 * UDIM + u];
        #pragma unroll
        for (int bb = 0; bb < 4; bb++) {
            gr[bb] = br; gz[bb] = bz; gn[bb] = bn;
            hr[bb] = cr; hz[bb] = cz; hn[bb] = cn;
        }
    }
    mv4b(Wih,                     INDIM, xs, xs + 128, xs + 256, xs + 384, ws, u, gr);
    mv4b(Wih + UDIM * INDIM,      INDIM, xs, xs + 128, xs + 256, xs + 384, ws, u, gz);
    mv4b(Wih + 2 * UDIM * INDIM,  INDIM, xs, xs + 128, xs + 256, xs + 384, ws, u, gn);
    mv4b(Whh,                     UDIM,  hs, hs + 256, hs + 512, hs + 768, ws, u, hr);
    mv4b(Whh + UDIM * UDIM,       UDIM,  hs, hs + 256, hs + 512, hs + 768, ws, u, hz);
    mv4b(Whh + 2 * UDIM * UDIM,   UDIM,  hs, hs + 256, hs + 512, hs + 768, ws, u, hn);

    #pragma unroll
    for (int bb = 0; bb < 4; bb++) {
        float r = sigm_f(gr[bb] + hr[bb]);
        float z = sigm_f(gz[bb] + hz[bb]);
        float n = tanh_f(gn[bb] + r * hn[bb]);
        float dv = (1.f - z) * n + z * hs[bb * 256 + u];
        dts[bb * 256 + u] = dv;
        int gi = (b0 + bb) * UDIM + u;
        g_dt[gi] = dv;
        out_dt[gi] = dv;
    }
    // query = d_t @ W2^T (dts read only after mv4b's first barrier)
    float q[4] = {0.f, 0.f, 0.f, 0.f};
    mv4b(W2, UDIM, dts, dts + 256, dts + 512, dts + 768, ws, u, q);
    #pragma unroll
    for (int bb = 0; bb < 4; bb++) g_query[(b0 + bb) * UDIM + u] = q[bb];
}

// ================= K1: fused keys-GEMM + tanh scores + online softmax + context =================
// 128 blocks (one per batch) x 512 threads (16 warps, 4x4 warp grid).
// Warp tile 32 rows x 64 n. Thread: rows rowbase + 4p (lo) / +16 (hi), n = nbase + 8j.
// K=256 in 16 double-buffered 16-k W1 slices (pre-duplicated ull). Inner k loop FULLY unrolled.
#define MT_STRIDE 260
#define WT2_ROW 257
#define WT2_HALF (16 * 257)
#define OFF_MT  0
#define OFF_WT2 (128 * MT_STRIDE)
#define OFF_SCP (OFF_WT2 + 2 * WT2_HALF * 2)
#define OFF_SC  (OFF_SCP + 4 * 132)
#define OFF_ES  (OFF_SC + 128)
#define OFF_ST  (OFF_ES + 128)
#define OFF_QS  (OFF_ST + 8)
#define OFF_VS  (OFF_QS + 256)
#define OFF_CTX (OFF_VS + 256)
#define K1_SMEM_FLOATS (OFF_CTX + 512)

__global__ __launch_bounds__(512, 1) void k1_attn(
    const float* __restrict__ memory, const float* __restrict__ W1,
    const float* __restrict__ vvec)
{
    extern __shared__ float sm[];
    float* Mt = sm + OFF_MT;
    ull*   Wt2 = (ull*)(sm + OFF_WT2);
    float* scp = sm + OFF_SCP;
    float* scores_s = sm + OFF_SC;
    float* e_s = sm + OFF_ES;
    float* st = sm + OFF_ST;
    float* q_s = sm + OFF_QS;
    float* v_s = sm + OFF_VS;
    float* ctx_s = sm + OFF_CTX;

    int tid = threadIdx.x;
    int b = blockIdx.x;
    int wid = tid >> 5, lane = tid & 31;
    int warpR = wid >> 2, warpC = wid & 3;
    int r_l = lane >> 3, c_l = lane & 7;
    int rowbase = warpR * 32 + r_l;          // thread rows: rowbase + 4p, rowbase + 4p + 16
    int nbase = warpC * 64 + c_l;            // n = nbase + 8j
    int uu = tid & 255, half = tid >> 8;

    for (int i = tid; i < 256; i += 512) {
        q_s[i] = g_query[b * UDIM + i];
        v_s[i] = vvec[i];
    }
    if (tid == 0) { st[0] = -1e30f; st[1] = 0.f; st[2] = 0.f; }

    float ctx = 0.f;
    float srun = 0.f;
    const float* memb = memory + (size_t)b * TLEN * UDIM;

    // slice staging: 512 threads x 2 float4 (n and n+128), 16 k per slice
    int sn0 = tid >> 2, skc = tid & 3;

    for (int tile = 0; tile < 8; tile++) {
        int t0 = tile * 128;
        __syncthreads();   // prev tile consumers done; smem reusable
        // --- load Mt[128][256] (stride 260) ---
        #pragma unroll
        for (int it = 0; it < 16; it++) {
            int idx = tid + it * 512;
            int m = idx >> 6, q = idx & 63;
            float4 vld = *(const float4*)(memb + (size_t)(t0 + m) * UDIM + q * 4);
            *(float4*)(Mt + m * MT_STRIDE + q * 4) = vld;
        }

        ull acc[4][8];
        #pragma unroll
        for (int p = 0; p < 4; p++)
            #pragma unroll
            for (int j = 0; j < 8; j++) acc[p][j] = 0ull;

        // prefetch slice 0
        float4 w0 = *(const float4*)(W1 + sn0 * UDIM + 0 + skc * 4);
        float4 w1 = *(const float4*)(W1 + (sn0 + 128) * UDIM + 0 + skc * 4);

        for (int s = 0; s < 16; s++) {
            // store current slice (duplicated {w,w}) into buffer s&1
            float* wf = (float*)(Wt2 + (s & 1) * WT2_HALF);
            {
                int kb = skc * 4;
                int i0 = ((kb + 0) * WT2_ROW + sn0) * 2;
                int i1 = ((kb + 1) * WT2_ROW + sn0) * 2;
                int i2 = ((kb + 2) * WT2_ROW + sn0) * 2;
                int i3 = ((kb + 3) * WT2_ROW + sn0) * 2;
                wf[i0] = w0.x; wf[i0 + 1] = w0.x;
                wf[i1] = w0.y; wf[i1 + 1] = w0.y;
                wf[i2] = w0.z; wf[i2 + 1] = w0.z;
                wf[i3] = w0.w; wf[i3 + 1] = w0.w;
                int j0 = i0 + 256, j1 = i1 + 256, j2 = i2 + 256, j3 = i3 + 256;
                wf[j0] = w1.x; wf[j0 + 1] = w1.x;
                wf[j1] = w1.y; wf[j1 + 1] = w1.y;
                wf[j2] = w1.z; wf[j2 + 1] = w1.z;
                wf[j3] = w1.w; wf[j3 + 1] = w1.w;
            }
            __syncthreads();
            // prefetch next slice while GEMM runs
            if (s < 15) {
                int kb = (s + 1) * 16;
                w0 = *(const float4*)(W1 + sn0 * UDIM + kb + skc * 4);
                w1 = *(const float4*)(W1 + (sn0 + 128) * UDIM + kb + skc * 4);
            }
            // --- GEMM on slice s (fully unrolled: all smem offsets immediate) ---
            const ull* wb = Wt2 + (s & 1) * WT2_HALF + nbase;
            const float* mb = Mt + rowbase * MT_STRIDE + s * 16;
            #pragma unroll
            for (int k = 0; k < 16; k++) {
                ull bfr[8];
                #pragma unroll
                for (int j = 0; j < 8; j++) bfr[j] = wb[k * WT2_ROW + 8 * j];
                #pragma unroll
                for (int p = 0; p < 4; p++) {
                    float alo = mb[(4 * p) * MT_STRIDE + k];
                    float ahi = mb[(4 * p + 16) * MT_STRIDE + k];
                    ull a = pk2(alo, ahi);
                    #pragma unroll
                    for (int j = 0; j < 8; j++) fma2(acc[p][j], a, bfr[j]);
                }
            }
        }

        // --- scores epilogue: s_row = sum_n v[n]*tanh(key + q[n]) ---
        {
            float qv[8], vv[8];
            #pragma unroll
            for (int j = 0; j < 8; j++) {
                qv[j] = q_s[nbase + 8 * j];
                vv[j] = v_s[nbase + 8 * j];
            }
            float slo[4] = {0.f, 0.f, 0.f, 0.f};
            float shi[4] = {0.f, 0.f, 0.f, 0.f};
            #pragma unroll
            for (int p = 0; p < 4; p++) {
                #pragma unroll
                for (int j = 0; j < 8; j++) {
                    float2 kv = unpk(acc[p][j]);
                    slo[p] = fmaf(vv[j], tanh_f(kv.x + qv[j]), slo[p]);
                    shi[p] = fmaf(vv[j], tanh_f(kv.y + qv[j]), shi[p]);
                }
            }
            #pragma unroll
            for (int p = 0; p < 4; p++) {
                #pragma unroll
                for (int off = 1; off <= 4; off <<= 1) {
                    slo[p] += __shfl_xor_sync(0xffffffffu, slo[p], off);
                    shi[p] += __shfl_xor_sync(0xffffffffu, shi[p], off);
                }
            }
            if (c_l == 0) {
                #pragma unroll
                for (int p = 0; p < 4; p++) {
                    scp[warpC * 132 + rowbase + 4 * p] = slo[p];
                    scp[warpC * 132 + rowbase + 4 * p + 16] = shi[p];
                }
            }
        }
        __syncthreads();
        if (tid < 128)
            scores_s[tid] = scp[tid] + scp[132 + tid] + scp[264 + tid] + scp[396 + tid];
        __syncthreads();
        if (tid < 32) {
            float mx = fmaxf(fmaxf(scores_s[tid], scores_s[tid + 32]),
                             fmaxf(scores_s[tid + 64], scores_s[tid + 96]));
            #pragma unroll
            for (int off = 16; off > 0; off >>= 1)
                mx = fmaxf(mx, __shfl_xor_sync(0xffffffffu, mx, off));
            if (tid == 0) {
                float m_old = st[0];
                float m_new = fmaxf(m_old, mx);
                st[2] = ex2f((m_old - m_new) * LOG2E);
                st[0] = m_new;
            }
        }
        __syncthreads();
        float scale = st[2];
        float m_new = st[0];
        ctx *= scale;
        if (tid < 128) {
            float e = ex2f((scores_s[tid] - m_new) * LOG2E);
            e_s[tid] = e;
            srun = srun * scale + e;
        }
        __syncthreads();  // e_s ready

        // --- context accumulation: ctx[u] += sum_t e[t]*Mt[t][u] ---
        int tstart = half * 64;
        #pragma unroll 4
        for (int t = 0; t < 64; t++)
            ctx = fmaf(e_s[tstart + t], Mt[(tstart + t) * MT_STRIDE + uu], ctx);
    }

    __syncthreads();
    if (tid < 128) scores_s[tid] = srun;
    ctx_s[half * 256 + uu] = ctx;
    __syncthreads();
    if (tid < 32) {
        float s = scores_s[tid] + scores_s[tid + 32] + scores_s[tid + 64] + scores_s[tid + 96];
        #pragma unroll
        for (int off = 16; off > 0; off >>= 1)
            s += __shfl_xor_sync(0xffffffffu, s, off);
        if (tid == 0) st[1] = s;
    }
    __syncthreads();
    float rinv = 1.f / st[1];
    if (tid < 256) g_ctx[b * UDIM + tid] = (ctx_s[tid] + ctx_s[256 + tid]) * rinv;
}

// ================= K2: proj -> GRU1 -> GRU2 -> out =================
// 32 blocks x 256 threads; 4 batches per block.
#define K2_CAT   0
#define K2_GI    (K2_CAT + 4 * 512)
#define K2_H1    (K2_GI + 4 * 256)
#define K2_H2    (K2_H1 + 4 * 256)
#define K2_G2IN  (K2_H2 + 4 * 256)
#define K2_BF    (K2_G2IN + 4 * 256)
#define K2_WS    (K2_BF + 4 * 256)
#define K2_SMEM_FLOATS (K2_WS + 2 * WS2_HALF)

__global__ __launch_bounds__(256) void k2_tail(
    const float* __restrict__ h1in, const float* __restrict__ h2in,
    const float* __restrict__ g1_Wih, const float* __restrict__ g1_Whh,
    const float* __restrict__ g1_bih, const float* __restrict__ g1_bhh,
    const float* __restrict__ g2_Wih, const float* __restrict__ g2_Whh,
    const float* __restrict__ g2_bih, const float* __restrict__ g2_bhh,
    const float* __restrict__ proj_W, const float* __restrict__ proj_b,
    const float* __restrict__ out_W, const float* __restrict__ out_b,
    float* __restrict__ out_all)
{
    extern __shared__ float sm[];
    float* cat  = sm + K2_CAT;    // [4][512]
    float* gi   = sm + K2_GI;     // [4][256]
    float* h1s  = sm + K2_H1;
    float* h2s  = sm + K2_H2;
    float* g2in = sm + K2_G2IN;
    float* bfs  = sm + K2_BF;
    float* ws   = sm + K2_WS;
    int u = threadIdx.x;
    int b0 = blockIdx.x * 4;

    for (int idx = u; idx < 4 * UDIM; idx += 256) {
        int bb = idx >> 8, j = idx & 255;
        cat[bb * 512 + j] = g_dt[(b0 + bb) * UDIM + j];
        cat[bb * 512 + UDIM + j] = g_ctx[(b0 + bb) * UDIM + j];
        h1s[bb * 256 + j] = h1in[(b0 + bb) * UDIM + j];
        h2s[bb * 256 + j] = h2in[(b0 + bb) * UDIM + j];
    }

    // ---- proj ----
    {
        float pb = proj_b[u];
        float a[4] = {pb, pb, pb, pb};
        mv4b(proj_W, 2 * UDIM, cat, cat + 512, cat + 1024, cat + 1536, ws, u, a);
        gi[u] = a[0]; gi[256 + u] = a[1]; gi[512 + u] = a[2]; gi[768 + u] = a[3];
    }

    // ---- GRU1 ----
    {
        float gr[4], gz[4], gn[4], hr[4], hz[4], hn[4];
        float br = g1_bih[u], bz = g1_bih[UDIM + u], bn = g1_bih[2 * UDIM + u];
        float cr = g1_bhh[u], cz = g1_bhh[UDIM + u], cn = g1_bhh[2 * UDIM + u];
        #pragma unroll
        for (int bb = 0; bb < 4; bb++) {
            gr[bb] = br; gz[bb] = bz; gn[bb] = bn;
            hr[bb] = cr; hz[bb] = cz; hn[bb] = cn;
        }
        mv4b(g1_Wih,                   UDIM, gi, gi + 256, gi + 512, gi + 768, ws, u, gr);
        mv4b(g1_Wih + UDIM * UDIM,     UDIM, gi, gi + 256, gi + 512, gi + 768, ws, u, gz);
        mv4b(g1_Wih + 2 * UDIM * UDIM, UDIM, gi, gi + 256, gi + 512, gi + 768, ws, u, gn);
        mv4b(g1_Whh,                   UDIM, h1s, h1s + 256, h1s + 512, h1s + 768, ws, u, hr);
        mv4b(g1_Whh + UDIM * UDIM,     UDIM, h1s, h1s + 256, h1s + 512, h1s + 768, ws, u, hz);
        mv4b(g1_Whh + 2 * UDIM * UDIM, UDIM, h1s, h1s + 256, h1s + 512, h1s + 768, ws, u, hn);
        #pragma unroll
        for (int bb = 0; bb < 4; bb++) {
            float r = sigm_f(gr[bb] + hr[bb]);
            float z = sigm_f(gz[bb] + hz[bb]);
            float n = tanh_f(gn[bb] + r * hn[bb]);
            float hnew = (1.f - z) * n + z * h1s[bb * 256 + u];
            out_all[OFF_G1 + (b0 + bb) * UDIM + u] = hnew;
            g2in[bb * 256 + u] = gi[bb * 256 + u] + hnew;
        }
    }

    // ---- GRU2 ----
    {
        float gr[4], gz[4], gn[4], hr[4], hz[4], hn[4];
        float br = g2_bih[u], bz = g2_bih[UDIM + u], bn = g2_bih[2 * UDIM + u];
        float cr = g2_bhh[u], cz = g2_bhh[UDIM + u], cn = g2_bhh[2 * UDIM + u];
        #pragma unroll
        for (int bb = 0; bb < 4; bb++) {
            gr[bb] = br; gz[bb] = bz; gn[bb] = bn;
            hr[bb] = cr; hz[bb] = cz; hn[bb] = cn;
        }
        mv4b(g2_Wih,                   UDIM, g2in, g2in + 256, g2in + 512, g2in + 768, ws, u, gr);
        mv4b(g2_Wih + UDIM * UDIM,     UDIM, g2in, g2in + 256, g2in + 512, g2in + 768, ws, u, gz);
        mv4b(g2_Wih + 2 * UDIM * UDIM, UDIM, g2in, g2in + 256, g2in + 512, g2in + 768, ws, u, gn);
        mv4b(g2_Whh,                   UDIM, h2s, h2s + 256, h2s + 512, h2s + 768, ws, u, hr);
        mv4b(g2_Whh + UDIM * UDIM,     UDIM, h2s, h2s + 256, h2s + 512, h2s + 768, ws, u, hz);
        mv4b(g2_Whh + 2 * UDIM * UDIM, UDIM, h2s, h2s + 256, h2s + 512, h2s + 768, ws, u, hn);
        #pragma unroll
        for (int bb = 0; bb < 4; bb++) {
            float r = sigm_f(gr[bb] + hr[bb]);
            float z = sigm_f(gz[bb] + hz[bb]);
            float n = tanh_f(gn[bb] + r * hn[bb]);
            float hnew = (1.f - z) * n + z * h2s[bb * 256 + u];
            out_all[OFF_G2 + (b0 + bb) * UDIM + u] = hnew;
            bfs[bb * 256 + u] = g2in[bb * 256 + u] + hnew;
        }
    }
    __syncthreads();

    // ---- output layer: [4 x 400] per-thread float4 streaming ----
    for (int o = u; o < OUTD; o += 256) {
        float ob = out_b[o];
        float a0 = ob, a1 = ob, a2 = ob, a3 = ob;
        const float4* w4 = (const float4*)(out_W + o * UDIM);
        #pragma unroll 8
        for (int j4 = 0; j4 < 64; j4++) {
            float4 w = w4[j4];
            int j = j4 * 4;
            a0 = fmaf(bfs[j], w.x, fmaf(bfs[j + 1], w.y, fmaf(bfs[j + 2], w.z, fmaf(bfs[j + 3], w.w, a0))));
            a1 = fmaf(bfs[256 + j], w.x, fmaf(bfs[257 + j], w.y, fmaf(bfs[258 + j], w.z, fmaf(bfs[259 + j], w.w, a1))));
            a2 = fmaf(bfs[512 + j], w.x, fmaf(bfs[513 + j], w.y, fmaf(bfs[514 + j], w.z, fmaf(bfs[515 + j], w.w, a2))));
            a3 = fmaf(bfs[768 + j], w.x, fmaf(bfs[769 + j], w.y, fmaf(bfs[770 + j], w.z, fmaf(bfs[771 + j], w.w, a3))));
        }
        out_all[(b0 + 0) * OUTD + o] = a0;
        out_all[(b0 + 1) * OUTD + o] = a1;
        out_all[(b0 + 2) * OUTD + o] = a2;
        out_all[(b0 + 3) * OUTD + o] = a3;
    }
}

extern "C" void kernel_launch(void* const* d_in, const int* in_sizes, int n_in,
                              void* d_out, int out_size) {
    const float* decoder_input = (const float*)d_in[0];
    const float* memory        = (const float*)d_in[1];
    const float* attn_hidden   = (const float*)d_in[2];
    const float* gru1_hidden   = (const float*)d_in[3];
    const float* gru2_hidden   = (const float*)d_in[4];
    const float* W1            = (const float*)d_in[5];
    const float* W2            = (const float*)d_in[6];
    const float* v             = (const float*)d_in[7];
    const float* attn_Wih      = (const float*)d_in[8];
    const float* attn_Whh      = (const float*)d_in[9];
    const float* attn_bih      = (const float*)d_in[10];
    const float* attn_bhh      = (const float*)d_in[11];
    const float* g1_Wih        = (const float*)d_in[12];
    const float* g1_Whh        = (const float*)d_in[13];
    const float* g1_bih        = (const float*)d_in[14];
    const float* g1_bhh        = (const float*)d_in[15];
    const float* g2_Wih        = (const float*)d_in[16];
    const float* g2_Whh        = (const float*)d_in[17];
    const float* g2_bih        = (const float*)d_in[18];
    const float* g2_bhh        = (const float*)d_in[19];
    const float* proj_W        = (const float*)d_in[20];
    const float* proj_b        = (const float*)d_in[21];
    const float* out_W         = (const float*)d_in[22];
    const float* out_b         = (const float*)d_in[23];
    float* out = (float*)d_out;

    int k0_smem = K0_SMEM_FLOATS * sizeof(float);
    int k1_smem = K1_SMEM_FLOATS * sizeof(float);
    int k2_smem = K2_SMEM_FLOATS * sizeof(float);
    cudaFuncSetAttribute(k0_attn_gru, cudaFuncAttributeMaxDynamicSharedMemorySize, k0_smem);
    cudaFuncSetAttribute(k1_attn, cudaFuncAttributeMaxDynamicSharedMemorySize, k1_smem);
    cudaFuncSetAttribute(k2_tail, cudaFuncAttributeMaxDynamicSharedMemorySize, k2_smem);

    k0_attn_gru<<<32, 256, k0_smem>>>(decoder_input, attn_hidden,
                                      attn_Wih, attn_Whh, attn_bih, attn_bhh,
                                      W2, out + OFF_DT);
    k1_attn<<<128, 512, k1_smem>>>(memory, W1, v);
    k2_tail<<<32, 256, k2_smem>>>(gru1_hidden, gru2_hidden,
                                  g1_Wih, g1_Whh, g1_bih, g1_bhh,
                                  g2_Wih, g2_Whh, g2_bih, g2_bhh,
                                  proj_W, proj_b, out_W, out_b, out);
}